// round 11
// baseline (speedup 1.0000x reference)
#include <cuda_runtime.h>

#define NN 100000
#define NE 600000
#define CIN 16
#define HW 48
#define NL 5
#define EB ((NE + 127) / 128)
#define SR 132                    // h/stash row stride (floats), bank-clean

typedef unsigned long long u64;

// ---- scratch (device globals: allocation-guard safe) ----
__device__ float  g_x1[NN * CIN];
__device__ float  g_x2[NN * CIN];
__device__ float  g_agg[NN * CIN];
__device__ float  g_cnt[NN];
__device__ float  g_ef1[(size_t)NE * HW];   // 115 MB intermediate edge features
__device__ double g_sl[2];

// ---- f32x2 helpers ----
__device__ __forceinline__ u64 fma2(u64 a, u64 b, u64 c) {
    u64 d;
    asm("fma.rn.f32x2 %0,%1,%2,%3;" : "=l"(d) : "l"(a), "l"(b), "l"(c));
    return d;
}
__device__ __forceinline__ u64 bcast2(float v) {
    u64 r;
    asm("mov.b64 %0,{%1,%1};" : "=l"(r) : "f"(v));
    return r;
}
union Q4 { float4 f4; u64 u[2]; };
union P2 { u64 u; float2 f; };

// ---------------------------------------------------------------------------
__global__ void zero_kernel(int phase) {
    int i = blockIdx.x * blockDim.x + threadIdx.x;
    if (i < NN * CIN) g_agg[i] = 0.f;
    if (i < NN)       g_cnt[i] = 0.f;
    if (phase == 0 && i < 2) g_sl[i] = 0.0;
}

// ---------------------------------------------------------------------------
// NodeConv message + scatter (f32x2-packed MLP: 16 outputs = 8 pair-accs).
__global__ __launch_bounds__(128) void nc_kernel(
    const float* __restrict__ x, const int* __restrict__ ei,
    const float* __restrict__ ang,
    const float* __restrict__ w0, const float* __restrict__ b0,
    const float* __restrict__ wh, const float* __restrict__ bh)
{
    __shared__ __align__(16) float sw0[33 * 16];
    __shared__ __align__(16) float sb0[16];
    __shared__ __align__(16) float swh[5 * 16 * 16];
    __shared__ __align__(16) float sbh[5 * 16];
    int t = threadIdx.x;
    for (int i = t; i < 33 * 16; i += 128) sw0[i] = w0[i];
    for (int i = t; i < 16;      i += 128) sb0[i] = b0[i];
    for (int i = t; i < 5 * 256; i += 128) swh[i] = wh[i];
    for (int i = t; i < 80;      i += 128) sbh[i] = bh[i];
    __syncthreads();

    int e = blockIdx.x * 128 + t;
    if (e >= NE) return;
    int s = ei[e];
    int d = ei[NE + e];

    float in[33];
    const float4* xd4 = (const float4*)(x + (size_t)d * CIN);
    const float4* xs4 = (const float4*)(x + (size_t)s * CIN);
    #pragma unroll
    for (int q = 0; q < 4; q++) {
        float4 v = xd4[q];
        in[q * 4 + 0] = v.x; in[q * 4 + 1] = v.y; in[q * 4 + 2] = v.z; in[q * 4 + 3] = v.w;
    }
    #pragma unroll
    for (int q = 0; q < 4; q++) {
        float4 v = xs4[q];
        in[16 + q * 4 + 0] = v.x; in[16 + q * 4 + 1] = v.y;
        in[16 + q * 4 + 2] = v.z; in[16 + q * 4 + 3] = v.w;
    }
    in[32] = ang[e];

    u64 acc[8];
    float h[16];
    #pragma unroll
    for (int jp = 0; jp < 8; jp++) acc[jp] = *(const u64*)(sb0 + 2 * jp);
    #pragma unroll
    for (int k = 0; k < 33; k++) {
        u64 vp = bcast2(in[k]);
        const float4* wr = (const float4*)(sw0 + k * 16);
        #pragma unroll
        for (int q = 0; q < 4; q++) {
            Q4 w; w.f4 = wr[q];
            acc[2 * q + 0] = fma2(vp, w.u[0], acc[2 * q + 0]);
            acc[2 * q + 1] = fma2(vp, w.u[1], acc[2 * q + 1]);
        }
    }
    #pragma unroll
    for (int jp = 0; jp < 8; jp++) {
        P2 p; p.u = acc[jp];
        h[2 * jp + 0] = fmaxf(p.f.x, 0.f);
        h[2 * jp + 1] = fmaxf(p.f.y, 0.f);
    }

    #pragma unroll 1
    for (int l = 0; l < NL; l++) {
        const float* wl = swh + l * 256;
        const float* bl = sbh + l * 16;
        #pragma unroll
        for (int jp = 0; jp < 8; jp++) acc[jp] = *(const u64*)(bl + 2 * jp);
        #pragma unroll
        for (int k = 0; k < 16; k++) {
            u64 vp = bcast2(h[k]);
            const float4* wr = (const float4*)(wl + k * 16);
            #pragma unroll
            for (int q = 0; q < 4; q++) {
                Q4 w; w.f4 = wr[q];
                acc[2 * q + 0] = fma2(vp, w.u[0], acc[2 * q + 0]);
                acc[2 * q + 1] = fma2(vp, w.u[1], acc[2 * q + 1]);
            }
        }
        #pragma unroll
        for (int jp = 0; jp < 8; jp++) {
            P2 p; p.u = acc[jp];
            h[2 * jp + 0] = fmaxf(p.f.x, 0.f);
            h[2 * jp + 1] = fmaxf(p.f.y, 0.f);
        }
    }

    #pragma unroll
    for (int j = 0; j < 16; j++) atomicAdd(&g_agg[(size_t)d * CIN + j], h[j]);
    atomicAdd(&g_cnt[d], 1.f);
}

// ---------------------------------------------------------------------------
__global__ void div_kernel(float* __restrict__ out) {
    int i = blockIdx.x * blockDim.x + threadIdx.x;
    if (i >= NN * CIN) return;
    float c = g_cnt[i / CIN];
    out[i] = g_agg[i] / fmaxf(c, 1.f);
}

// ---------------------------------------------------------------------------
// EdgeConv as block-tiled GEMM: 128 rows (64 edges x 2 symmetric passes) x 48
// outputs per block. Hidden state h lives in smem [j][row] (stride SR=132).
// Thread (tc=t&3, tr=t>>2) owns 4 rows x 12 outputs: per k it issues 4 LDS.128
// (3 weight quads + 1 h quad, all broadcast/conflict-free) feeding 24 FFMA2.
// IS_EC1=1: combine [fe, action](49) -> 48, out = g_ef1
// IS_EC1=0: combine [fe, ef1](96)   -> 1,  out = d_out
template <int IS_EC1>
__global__ __launch_bounds__(128, 2) void ec_kernel(
    const float* __restrict__ x, const int* __restrict__ ei,
    const float* __restrict__ extra,
    const float* __restrict__ w0, const float* __restrict__ b0,
    const float* __restrict__ wh, const float* __restrict__ bh,
    const float* __restrict__ wc, const float* __restrict__ bc,
    float* __restrict__ out, int sli)
{
    extern __shared__ float smem[];
    const int WCN = IS_EC1 ? 49 * 48 : 96;   // padded alloc == real count here
    const int BCN = IS_EC1 ? 48 : 16;
    const int BCR = IS_EC1 ? 48 : 1;
    float* sw0   = smem;                 // 1536
    float* sb0   = sw0 + 1536;           // 48
    float* swh   = sb0 + 48;             // 11520
    float* sbh   = swh + 11520;          // 240
    float* swc   = sbh + 240;            // WCN
    float* sbc   = swc + WCN;            // BCN
    float* stash = sbc + BCN;            // 32*SR
    float* hb    = stash + 32 * SR;      // 48*SR

    int t = threadIdx.x;
    for (int i = t; i < 1536;  i += 128) sw0[i] = w0[i];
    for (int i = t; i < 48;    i += 128) sb0[i] = b0[i];
    for (int i = t; i < 11520; i += 128) swh[i] = wh[i];
    for (int i = t; i < 240;   i += 128) sbh[i] = bh[i];
    for (int i = t; i < WCN;   i += 128) swc[i] = (i < (IS_EC1 ? 2352 : 96)) ? wc[i] : 0.f;
    for (int i = t; i < BCN;   i += 128) sbc[i] = (i < BCR) ? bc[i] : 0.f;

    // ---- gather endpoint features into stash ----
    // rows 0..63  = pass0 (input order [xd, xs]) for edges e0..e0+63
    // rows 64..127= pass1 (input order [xs, xd])
    {
        int el = t & 63;
        int e  = blockIdx.x * 64 + el;
        int isD = (t < 64);                       // low threads fetch x[dst]
        int idx = isD ? ei[NE + e] : ei[e];
        int k0  = isD ? 0 : 16;                   // slot in pass0 row
        int k1  = 16 - k0;                        // slot in pass1 row
        const float4* xp = (const float4*)(x + (size_t)idx * CIN);
        #pragma unroll
        for (int q = 0; q < 4; q++) {
            float4 v = xp[q];
            float vv[4] = {v.x, v.y, v.z, v.w};
            #pragma unroll
            for (int c = 0; c < 4; c++) {
                int k = q * 4 + c;
                stash[(k0 + k) * SR + el]      = vv[c];
                stash[(k1 + k) * SR + 64 + el] = vv[c];
            }
        }
    }
    __syncthreads();

    int tc = t & 3;
    int tr = t >> 2;            // 0..31
    int rbase = tr * 4;         // rows rbase..rbase+3
    int ob = tc * 12;           // outputs ob..ob+11

    u64 acc[4][6];

    // ---- layer 0: 32 -> 48, src = stash ----
    {
        u64 bias[6];
        {
            const float4* bq = (const float4*)(sb0 + ob);
            #pragma unroll
            for (int q = 0; q < 3; q++) { Q4 b; b.f4 = bq[q]; bias[2*q] = b.u[0]; bias[2*q+1] = b.u[1]; }
        }
        #pragma unroll
        for (int r = 0; r < 4; r++)
            #pragma unroll
            for (int p = 0; p < 6; p++) acc[r][p] = bias[p];

        #pragma unroll 4
        for (int k = 0; k < 32; k++) {
            float4 hq = *(const float4*)(stash + k * SR + rbase);
            const float4* wr = (const float4*)(sw0 + k * 48 + ob);
            Q4 wq0, wq1, wq2; wq0.f4 = wr[0]; wq1.f4 = wr[1]; wq2.f4 = wr[2];
            float hv[4] = {hq.x, hq.y, hq.z, hq.w};
            #pragma unroll
            for (int r = 0; r < 4; r++) {
                u64 p = bcast2(hv[r]);
                acc[r][0] = fma2(p, wq0.u[0], acc[r][0]);
                acc[r][1] = fma2(p, wq0.u[1], acc[r][1]);
                acc[r][2] = fma2(p, wq1.u[0], acc[r][2]);
                acc[r][3] = fma2(p, wq1.u[1], acc[r][3]);
                acc[r][4] = fma2(p, wq2.u[0], acc[r][4]);
                acc[r][5] = fma2(p, wq2.u[1], acc[r][5]);
            }
        }
        // relu + store h (j-major, 4 rows per STS.128)
        #pragma unroll
        for (int pp = 0; pp < 6; pp++) {
            P2 a0, a1, a2, a3;
            a0.u = acc[0][pp]; a1.u = acc[1][pp]; a2.u = acc[2][pp]; a3.u = acc[3][pp];
            int j = ob + 2 * pp;
            *(float4*)(hb + j * SR + rbase) =
                make_float4(fmaxf(a0.f.x,0.f), fmaxf(a1.f.x,0.f), fmaxf(a2.f.x,0.f), fmaxf(a3.f.x,0.f));
            *(float4*)(hb + (j+1) * SR + rbase) =
                make_float4(fmaxf(a0.f.y,0.f), fmaxf(a1.f.y,0.f), fmaxf(a2.f.y,0.f), fmaxf(a3.f.y,0.f));
        }
    }
    __syncthreads();

    // ---- hidden layers: 48 -> 48, x5 ----
    #pragma unroll 1
    for (int l = 0; l < NL; l++) {
        const float* wl = swh + l * 2304;
        const float* bl = sbh + l * 48;
        u64 bias[6];
        {
            const float4* bq = (const float4*)(bl + ob);
            #pragma unroll
            for (int q = 0; q < 3; q++) { Q4 b; b.f4 = bq[q]; bias[2*q] = b.u[0]; bias[2*q+1] = b.u[1]; }
        }
        #pragma unroll
        for (int r = 0; r < 4; r++)
            #pragma unroll
            for (int p = 0; p < 6; p++) acc[r][p] = bias[p];

        #pragma unroll 4
        for (int k = 0; k < 48; k++) {
            float4 hq = *(const float4*)(hb + k * SR + rbase);
            const float4* wr = (const float4*)(wl + k * 48 + ob);
            Q4 wq0, wq1, wq2; wq0.f4 = wr[0]; wq1.f4 = wr[1]; wq2.f4 = wr[2];
            float hv[4] = {hq.x, hq.y, hq.z, hq.w};
            #pragma unroll
            for (int r = 0; r < 4; r++) {
                u64 p = bcast2(hv[r]);
                acc[r][0] = fma2(p, wq0.u[0], acc[r][0]);
                acc[r][1] = fma2(p, wq0.u[1], acc[r][1]);
                acc[r][2] = fma2(p, wq1.u[0], acc[r][2]);
                acc[r][3] = fma2(p, wq1.u[1], acc[r][3]);
                acc[r][4] = fma2(p, wq2.u[0], acc[r][4]);
                acc[r][5] = fma2(p, wq2.u[1], acc[r][5]);
            }
        }
        __syncthreads();   // all reads of hb complete
        #pragma unroll
        for (int pp = 0; pp < 6; pp++) {
            P2 a0, a1, a2, a3;
            a0.u = acc[0][pp]; a1.u = acc[1][pp]; a2.u = acc[2][pp]; a3.u = acc[3][pp];
            int j = ob + 2 * pp;
            *(float4*)(hb + j * SR + rbase) =
                make_float4(fmaxf(a0.f.x,0.f), fmaxf(a1.f.x,0.f), fmaxf(a2.f.x,0.f), fmaxf(a3.f.x,0.f));
            *(float4*)(hb + (j+1) * SR + rbase) =
                make_float4(fmaxf(a0.f.y,0.f), fmaxf(a1.f.y,0.f), fmaxf(a2.f.y,0.f), fmaxf(a3.f.y,0.f));
        }
        __syncthreads();
    }

    // ---- fold: side loss + fe (fe overwrites pass0 slots of hb) ----
    float sq = 0.f;
    {
        int fe = t & 63;               // edge-local
        int j0 = (t >> 6) * 24;        // half the j range per thread group
        #pragma unroll 4
        for (int jj = 0; jj < 24; jj++) {
            int j = j0 + jj;
            float a = hb[j * SR + fe];
            float b = hb[j * SR + 64 + fe];
            float dl = a - b;
            sq += dl * dl;
            hb[j * SR + fe] = 0.5f * (a + b);
        }
    }
    __syncthreads();

    // ---- combine layer ----
    if (IS_EC1) {
        // thread: outputs ob..ob+11 for edges e0=2*tr, e0+1
        int el = 2 * tr;
        int e0 = blockIdx.x * 64 + el;
        u64 o[2][6];
        {
            const float4* bq = (const float4*)(sbc + ob);
            #pragma unroll
            for (int q = 0; q < 3; q++) {
                Q4 b; b.f4 = bq[q];
                o[0][2*q] = b.u[0]; o[0][2*q+1] = b.u[1];
                o[1][2*q] = b.u[0]; o[1][2*q+1] = b.u[1];
            }
        }
        {   // action row (row 48)
            float a0 = extra[e0], a1 = extra[e0 + 1];
            const float4* wr = (const float4*)(swc + 48 * 48 + ob);
            Q4 wq0, wq1, wq2; wq0.f4 = wr[0]; wq1.f4 = wr[1]; wq2.f4 = wr[2];
            u64 p0 = bcast2(a0), p1 = bcast2(a1);
            o[0][0]=fma2(p0,wq0.u[0],o[0][0]); o[0][1]=fma2(p0,wq0.u[1],o[0][1]);
            o[0][2]=fma2(p0,wq1.u[0],o[0][2]); o[0][3]=fma2(p0,wq1.u[1],o[0][3]);
            o[0][4]=fma2(p0,wq2.u[0],o[0][4]); o[0][5]=fma2(p0,wq2.u[1],o[0][5]);
            o[1][0]=fma2(p1,wq0.u[0],o[1][0]); o[1][1]=fma2(p1,wq0.u[1],o[1][1]);
            o[1][2]=fma2(p1,wq1.u[0],o[1][2]); o[1][3]=fma2(p1,wq1.u[1],o[1][3]);
            o[1][4]=fma2(p1,wq2.u[0],o[1][4]); o[1][5]=fma2(p1,wq2.u[1],o[1][5]);
        }
        #pragma unroll 4
        for (int k = 0; k < 48; k++) {
            float2 fp = *(const float2*)(hb + k * SR + el);
            const float4* wr = (const float4*)(swc + k * 48 + ob);
            Q4 wq0, wq1, wq2; wq0.f4 = wr[0]; wq1.f4 = wr[1]; wq2.f4 = wr[2];
            u64 p0 = bcast2(fp.x), p1 = bcast2(fp.y);
            o[0][0]=fma2(p0,wq0.u[0],o[0][0]); o[0][1]=fma2(p0,wq0.u[1],o[0][1]);
            o[0][2]=fma2(p0,wq1.u[0],o[0][2]); o[0][3]=fma2(p0,wq1.u[1],o[0][3]);
            o[0][4]=fma2(p0,wq2.u[0],o[0][4]); o[0][5]=fma2(p0,wq2.u[1],o[0][5]);
            o[1][0]=fma2(p1,wq0.u[0],o[1][0]); o[1][1]=fma2(p1,wq0.u[1],o[1][1]);
            o[1][2]=fma2(p1,wq1.u[0],o[1][2]); o[1][3]=fma2(p1,wq1.u[1],o[1][3]);
            o[1][4]=fma2(p1,wq2.u[0],o[1][4]); o[1][5]=fma2(p1,wq2.u[1],o[1][5]);
        }
        #pragma unroll
        for (int i = 0; i < 2; i++) {
            #pragma unroll
            for (int q = 0; q < 3; q++) {
                P2 p0, p1; p0.u = o[i][2*q]; p1.u = o[i][2*q+1];
                *(float4*)(out + (size_t)(e0 + i) * 48 + ob + q * 4) =
                    make_float4(p0.f.x, p0.f.y, p1.f.x, p1.f.y);
            }
        }
    } else {
        if (t < 64) {
            int e = blockIdx.x * 64 + t;
            float o = sbc[0];
            #pragma unroll 8
            for (int k = 0; k < 48; k++) o += hb[k * SR + t] * swc[k];
            const float4* ef = (const float4*)(extra + (size_t)e * 48);
            #pragma unroll
            for (int q = 0; q < 12; q++) {
                float4 v = ef[q];
                o += v.x * swc[48 + q * 4 + 0];
                o += v.y * swc[48 + q * 4 + 1];
                o += v.z * swc[48 + q * 4 + 2];
                o += v.w * swc[48 + q * 4 + 3];
            }
            out[e] = o;
        }
    }

    // side-loss reduction: warp shfl -> double atomic
    #pragma unroll
    for (int off = 16; off; off >>= 1)
        sq += __shfl_xor_sync(0xffffffffu, sq, off);
    if ((t & 31) == 0)
        atomicAdd(&g_sl[sli], (double)sq);
}

// ---------------------------------------------------------------------------
__global__ void fin_kernel(float* __restrict__ out) {
    double inv = 1.0 / ((double)NE * 48.0);
    out[NE] = (float)(0.5 * (g_sl[0] * inv + g_sl[1] * inv));
}

// ---------------------------------------------------------------------------
extern "C" void kernel_launch(void* const* d_in, const int* in_sizes, int n_in,
                              void* d_out, int out_size)
{
    const float* nf   = (const float*)d_in[0];
    const int*   ei   = (const int*)d_in[1];
    const float* ang  = (const float*)d_in[2];
    const float* act  = (const float*)d_in[4];
    const float* n1w0 = (const float*)d_in[5],  *n1b0 = (const float*)d_in[6];
    const float* n1wh = (const float*)d_in[7],  *n1bh = (const float*)d_in[8];
    const float* n2w0 = (const float*)d_in[9],  *n2b0 = (const float*)d_in[10];
    const float* n2wh = (const float*)d_in[11], *n2bh = (const float*)d_in[12];
    const float* e1w0 = (const float*)d_in[13], *e1b0 = (const float*)d_in[14];
    const float* e1wh = (const float*)d_in[15], *e1bh = (const float*)d_in[16];
    const float* e1wc = (const float*)d_in[17], *e1bc = (const float*)d_in[18];
    const float* e2w0 = (const float*)d_in[19], *e2b0 = (const float*)d_in[20];
    const float* e2wh = (const float*)d_in[21], *e2bh = (const float*)d_in[22];
    const float* e2wc = (const float*)d_in[23], *e2bc = (const float*)d_in[24];
    float* out = (float*)d_out;

    void *px1, *px2, *pef1;
    cudaGetSymbolAddress(&px1, g_x1);
    cudaGetSymbolAddress(&px2, g_x2);
    cudaGetSymbolAddress(&pef1, g_ef1);

    // smem: weights + stash(32*SR) + hbuf(48*SR)
    size_t sh1 = (size_t)(1536 + 48 + 11520 + 240 + 49 * 48 + 48 + 32 * SR + 48 * SR) * sizeof(float);
    size_t sh2 = (size_t)(1536 + 48 + 11520 + 240 + 96 + 16 + 32 * SR + 48 * SR) * sizeof(float);
    cudaFuncSetAttribute(ec_kernel<1>, cudaFuncAttributeMaxDynamicSharedMemorySize, (int)sh1);
    cudaFuncSetAttribute(ec_kernel<0>, cudaFuncAttributeMaxDynamicSharedMemorySize, (int)sh2);
    cudaFuncSetAttribute(ec_kernel<1>, cudaFuncAttributePreferredSharedMemoryCarveout, 100);
    cudaFuncSetAttribute(ec_kernel<0>, cudaFuncAttributePreferredSharedMemoryCarveout, 100);

    const int ECB = NE / 64;   // 9375 blocks, exact

    // NodeConv1 -> x1
    zero_kernel<<<6250, 256>>>(0);
    nc_kernel<<<EB, 128>>>(nf, ei, ang, n1w0, n1b0, n1wh, n1bh);
    div_kernel<<<6250, 256>>>((float*)px1);
    // EdgeConv1 -> ef1 (E x 48), sl[0]
    ec_kernel<1><<<ECB, 128, sh1>>>((const float*)px1, ei, act,
                                    e1w0, e1b0, e1wh, e1bh, e1wc, e1bc,
                                    (float*)pef1, 0);
    // NodeConv2 -> x2
    zero_kernel<<<6250, 256>>>(1);
    nc_kernel<<<EB, 128>>>((const float*)px1, ei, ang, n2w0, n2b0, n2wh, n2bh);
    div_kernel<<<6250, 256>>>((float*)px2);
    // EdgeConv2 -> out (E x 1), sl[1]
    ec_kernel<0><<<ECB, 128, sh2>>>((const float*)px2, ei, (const float*)pef1,
                                    e2w0, e2b0, e2wh, e2bh, e2wc, e2bc,
                                    out, 1);
    if (out_size > NE) fin_kernel<<<1, 1>>>(out);
}